// round 3
// baseline (speedup 1.0000x reference)
#include <cuda_runtime.h>

#define DD 128
#define ROWS 8192
#define NTRIU 8256          // DD*(DD+1)/2
#define NQ 2064             // NTRIU / 4
#define OUT_ROW 8384        // DD + NTRIU

__global__ __launch_bounds__(256, 8)
void poly_kernel(const float* __restrict__ x,
                 const float* __restrict__ scales,
                 float* __restrict__ out) {
    __shared__ float xs[DD];     // normalized row
    __shared__ float xs2[DD];    // normalized row * scale2
    __shared__ float partial[8];

    const int row = blockIdx.x;
    const int tid = threadIdx.x;

    // ---- load + sum of squares ----
    const float* xr = x + (size_t)row * DD;
    float v = (tid < DD) ? xr[tid] : 0.0f;
    float ss = v * v;
    #pragma unroll
    for (int o = 16; o; o >>= 1)
        ss += __shfl_xor_sync(0xffffffffu, ss, o);
    if ((tid & 31) == 0) partial[tid >> 5] = ss;
    __syncthreads();

    float s = 0.0f;
    #pragma unroll
    for (int w = 0; w < 8; w++) s += partial[w];

    const float inv = 1.0f / fmaxf(sqrtf(s), 1e-12f);
    const float s2 = __ldg(scales + 1);

    float* orow = out + (size_t)row * OUT_ROW;
    const float xn = v * inv;
    if (tid < DD) {
        xs[tid]  = xn;
        xs2[tid] = xn * s2;
        orow[tid] = xn;          // degree-1 features (unscaled)
    }
    __syncthreads();

    // ---- degree-2 upper-triangular products, float4-vectorized ----
    // flattened triu index t in [0, NTRIU); row i's segment: [base(i), base(i) + (DD-i))
    float* odeg2 = orow + DD;
    int i = 0, bb = 0, ll = DD;          // cursor: current i, base(i), segment length
    for (int q = tid; q < NQ; q += 256) {
        const int t = q * 4;
        // advance cursor to the segment containing t (monotone across iterations)
        while (t >= bb + ll) { bb += ll; ll--; i++; }

        int ii = i, b = bb, l = ll;
        int te = t;
        // segment lengths are >= 1, so +1 on te crosses at most one boundary
        float r0 = xs2[ii] * xs[ii + (te - b)];
        te++; if (te >= b + l) { b += l; l--; ii++; }
        float r1 = xs2[ii] * xs[ii + (te - b)];
        te++; if (te >= b + l) { b += l; l--; ii++; }
        float r2 = xs2[ii] * xs[ii + (te - b)];
        te++; if (te >= b + l) { b += l; l--; ii++; }
        float r3 = xs2[ii] * xs[ii + (te - b)];

        *reinterpret_cast<float4*>(odeg2 + t) = make_float4(r0, r1, r2, r3);
    }
}

extern "C" void kernel_launch(void* const* d_in, const int* in_sizes, int n_in,
                              void* d_out, int out_size) {
    const float* x      = (const float*)d_in[0];
    const float* scales = (const float*)d_in[1];
    float* out          = (float*)d_out;
    poly_kernel<<<ROWS, 256>>>(x, scales, out);
}

// round 8
// speedup vs baseline: 1.0321x; 1.0321x over previous
#include <cuda_runtime.h>

#define DD 128
#define ROWS 8192
#define NTRIU 8256          // DD*(DD+1)/2
#define OUT_ROW 8384        // DD + NTRIU

__global__ __launch_bounds__(256, 8)
void poly_kernel(const float* __restrict__ x,
                 const float* __restrict__ scales,
                 float* __restrict__ out) {
    __shared__ float xs[DD];     // normalized row
    __shared__ float xs2[DD];    // normalized row * scale2
    __shared__ float partial[8];

    const int row = blockIdx.x;
    const int tid = threadIdx.x;

    // ---- load + sum of squares ----
    const float* xr = x + (size_t)row * DD;
    float v = (tid < DD) ? xr[tid] : 0.0f;
    float ss = v * v;
    #pragma unroll
    for (int o = 16; o; o >>= 1)
        ss += __shfl_xor_sync(0xffffffffu, ss, o);
    if ((tid & 31) == 0) partial[tid >> 5] = ss;
    __syncthreads();

    float s = 0.0f;
    #pragma unroll
    for (int w = 0; w < 8; w++) s += partial[w];

    const float inv = 1.0f / fmaxf(sqrtf(s), 1e-12f);
    const float s2 = __ldg(scales + 1);

    float* orow = out + (size_t)row * OUT_ROW;
    const float xn = v * inv;
    if (tid < DD) {
        xs[tid]  = xn;
        xs2[tid] = xn * s2;
        orow[tid] = xn;          // degree-1 features (unscaled)
    }
    __syncthreads();

    // ---- degree-2: segment-major, conflict-free, coalesced ----
    // Segment i: outputs odeg2[base(i) .. base(i)+len), len = DD - i,
    //            base(i) = i*(2*DD + 1 - i)/2, value = xs2[i] * xs[i + d].
    // Warp w handles pairs (i, 127-i) for i = 8k + w -> 129 elts/pair, 8 pairs,
    // perfectly balanced across the 8 warps.
    float* odeg2 = orow + DD;
    const int warp = tid >> 5;
    const int lane = tid & 31;

    #pragma unroll
    for (int k = 0; k < 8; k++) {
        const int iA = 8 * k + warp;          // 0..63
        {
            const int i   = iA;
            const int len = DD - i;
            const int base = (i * (2 * DD + 1 - i)) >> 1;
            const float a = xs2[i];
            float* o = odeg2 + base;
            const float* xp = xs + i;
            #pragma unroll 4
            for (int d = lane; d < len; d += 32)
                o[d] = a * xp[d];
        }
        {
            const int i   = (DD - 1) - iA;    // 127..64
            const int len = DD - i;
            const int base = (i * (2 * DD + 1 - i)) >> 1;
            const float a = xs2[i];
            float* o = odeg2 + base;
            const float* xp = xs + i;
            #pragma unroll 4
            for (int d = lane; d < len; d += 32)
                o[d] = a * xp[d];
        }
    }
}

extern "C" void kernel_launch(void* const* d_in, const int* in_sizes, int n_in,
                              void* d_out, int out_size) {
    const float* x      = (const float*)d_in[0];
    const float* scales = (const float*)d_in[1];
    float* out          = (float*)d_out;
    poly_kernel<<<ROWS, 256>>>(x, scales, out);
}

// round 9
// speedup vs baseline: 1.3690x; 1.3264x over previous
#include <cuda_runtime.h>

#define DD 128
#define ROWS 8192
#define NTRIU 8256          // DD*(DD+1)/2
#define OUT_ROW 8384        // DD + NTRIU
#define REP_STRIDE 129      // replicated-copy stride (conflict-free quad gather)

__global__ __launch_bounds__(256, 8)
void poly_kernel(const float* __restrict__ x,
                 const float* __restrict__ scales,
                 float* __restrict__ out) {
    __shared__ float xsrep[4 * REP_STRIDE];  // 4 copies of normalized row
    __shared__ float xs2[DD];                // normalized row * scale2
    __shared__ float partial[8];

    const int row = blockIdx.x;
    const int tid = threadIdx.x;

    // ---- load + sum of squares ----
    const float* xr = x + (size_t)row * DD;
    float v = (tid < DD) ? xr[tid] : 0.0f;
    float ss = v * v;
    #pragma unroll
    for (int o = 16; o; o >>= 1)
        ss += __shfl_xor_sync(0xffffffffu, ss, o);
    if ((tid & 31) == 0) partial[tid >> 5] = ss;
    __syncthreads();

    float s = 0.0f;
    #pragma unroll
    for (int w = 0; w < 8; w++) s += partial[w];

    const float inv = 1.0f / fmaxf(sqrtf(s), 1e-12f);
    const float s2 = __ldg(scales + 1);

    float* orow = out + (size_t)row * OUT_ROW;
    const float xn = v * inv;
    if (tid < DD) {
        xsrep[tid]                  = xn;
        xsrep[REP_STRIDE + tid]     = xn;
        xsrep[2 * REP_STRIDE + tid] = xn;
        xsrep[3 * REP_STRIDE + tid] = xn;
        xs2[tid] = xn * s2;
        orow[tid] = xn;              // degree-1 features (unscaled)
    }
    __syncthreads();

    // ---- degree-2: segment-major, aligned float4 stores, conflict-free gather ----
    // Segment i: odeg2[base(i) .. base(i)+len), len = DD-i, base(i)=i*(257-i)/2,
    // value = xs2[i] * xn[i + d].
    // Warp w handles pairs (i, 127-i), i = 8k + w -> 129 elts/pair, 8 pairs/warp.
    float* odeg2 = orow + DD;
    const int warp = tid >> 5;
    const int lane = tid & 31;
    // per-lane base into the replicated copies: copy (lane>>3), quad offset 4*lane
    const int rep_base = (lane >> 3) * REP_STRIDE + 4 * lane;

    #pragma unroll
    for (int k = 0; k < 8; k++) {
        const int iA = 8 * k + warp;          // 0..63
        #pragma unroll
        for (int m = 0; m < 2; m++) {
            const int i   = m ? (DD - 1) - iA : iA;
            const int len = DD - i;
            const int base = (i * (2 * DD + 1 - i)) >> 1;
            const float a = xs2[i];
            float* o = odeg2 + base;

            const int h   = (4 - (base & 3)) & 3;       // scalar head to align
            const int hc  = h < len ? h : len;
            if (lane < hc)
                o[lane] = a * xsrep[i + lane];

            const int nq4 = (len > h) ? ((len - h) >> 2) : 0;   // <= 32
            if (lane < nq4) {
                const int d = h + 4 * lane;
                const float* src = xsrep + rep_base + i + h;    // xn[i+d..i+d+3]
                float4 r;
                r.x = a * src[0];
                r.y = a * src[1];
                r.z = a * src[2];
                r.w = a * src[3];
                *reinterpret_cast<float4*>(o + d) = r;
            }

            const int ts  = h + 4 * nq4;                 // scalar tail
            const int rem = len - ts;
            if (lane < rem)
                o[ts + lane] = a * xsrep[i + ts + lane];
        }
    }
}

extern "C" void kernel_launch(void* const* d_in, const int* in_sizes, int n_in,
                              void* d_out, int out_size) {
    const float* x      = (const float*)d_in[0];
    const float* scales = (const float*)d_in[1];
    float* out          = (float*)d_out;
    poly_kernel<<<ROWS, 256>>>(x, scales, out);
}

// round 10
// speedup vs baseline: 1.7442x; 1.2741x over previous
#include <cuda_runtime.h>

#define DD 128
#define ROWS 8192
#define NTRIU 8256          // DD*(DD+1)/2
#define NQ 2064             // NTRIU / 4
#define OUT_ROW 8384        // DD + NTRIU
#define RS 129              // replicated-copy stride (conflict-free gather)

__global__ __launch_bounds__(256, 8)
void poly_kernel(const float* __restrict__ x,
                 const float* __restrict__ scales,
                 float* __restrict__ out) {
    __shared__ float xsrep[4 * RS];  // 4 copies of normalized row
    __shared__ float xs2[DD];        // normalized row * scale2
    __shared__ float partial[8];

    const int row = blockIdx.x;
    const int tid = threadIdx.x;

    // ---- load + sum of squares ----
    const float* xr = x + (size_t)row * DD;
    float v = (tid < DD) ? xr[tid] : 0.0f;
    float ss = v * v;
    #pragma unroll
    for (int o = 16; o; o >>= 1)
        ss += __shfl_xor_sync(0xffffffffu, ss, o);
    if ((tid & 31) == 0) partial[tid >> 5] = ss;
    __syncthreads();

    float s = 0.0f;
    #pragma unroll
    for (int w = 0; w < 8; w++) s += partial[w];

    const float inv = 1.0f / fmaxf(sqrtf(s), 1e-12f);
    const float s2 = __ldg(scales + 1);

    float* orow = out + (size_t)row * OUT_ROW;
    const float xn = v * inv;
    if (tid < DD) {
        xsrep[tid]          = xn;
        xsrep[RS + tid]     = xn;
        xsrep[2 * RS + tid] = xn;
        xsrep[3 * RS + tid] = xn;
        xs2[tid] = xn * s2;
        orow[tid] = xn;              // degree-1 features (unscaled)
    }
    __syncthreads();

    // ---- degree-2: flat aligned-quad stream ----
    // t in [0, NTRIU); segment i covers [base(i), base(i)+DD-i), base(i)=i*(257-i)/2.
    // Per quad: i = floor((257 - sqrt(257^2 - 8t))/2)  (exact in fp32, see analysis),
    // then walk 4 elements with a 1-op boundary check. All stores are aligned STG.128.
    float* odeg2 = orow + DD;
    const int lane = tid & 31;
    const float* xj = xsrep + (lane >> 3) * RS;   // this lane's replica

    for (int q = tid; q < NQ; q += 256) {
        const int t = 4 * q;
        const float disc = (float)(66049 - 8 * t);       // 257^2 - 8t, exact in fp32
        const float rt = __fsqrt_rn(disc);
        int i = (int)((257.0f - rt) * 0.5f);
        const int base = (i * (257 - i)) >> 1;
        int j = i + (t - base);

        float4 o;
        o.x = xs2[i] * xj[j];
        j++; if (j >= DD) { i++; j = i; }
        o.y = xs2[i] * xj[j];
        j++; if (j >= DD) { i++; j = i; }
        o.z = xs2[i] * xj[j];
        j++; if (j >= DD) { i++; j = i; }
        o.w = xs2[i] * xj[j];

        *reinterpret_cast<float4*>(odeg2 + t) = o;
    }
}

extern "C" void kernel_launch(void* const* d_in, const int* in_sizes, int n_in,
                              void* d_out, int out_size) {
    const float* x      = (const float*)d_in[0];
    const float* scales = (const float*)d_in[1];
    float* out          = (float*)d_out;
    poly_kernel<<<ROWS, 256>>>(x, scales, out);
}

// round 13
// speedup vs baseline: 1.9853x; 1.1382x over previous
#include <cuda_runtime.h>

#define DD 128
#define ROWS 8192
#define NTRIU 8256          // DD*(DD+1)/2
#define NQ 2064             // NTRIU / 4
#define OUT_ROW 8384        // DD + NTRIU
#define RS 129              // replicated-copy stride (conflict-free gather)

__device__ __forceinline__ float rsqrt_approx(float x) {
    float r;
    asm("rsqrt.approx.f32 %0, %1;" : "=f"(r) : "f"(x));
    return r;
}

__global__ __launch_bounds__(256, 8)
void poly_kernel(const float* __restrict__ x,
                 const float* __restrict__ scales,
                 float* __restrict__ out) {
    __shared__ float xsrep[4 * RS];  // 4 copies of normalized row
    __shared__ float xs2[DD];        // normalized row * scale2
    __shared__ float partial[8];

    const int row = blockIdx.x;
    const int tid = threadIdx.x;

    // ---- load + sum of squares ----
    const float* xr = x + (size_t)row * DD;
    float v = (tid < DD) ? xr[tid] : 0.0f;
    float ss = v * v;
    #pragma unroll
    for (int o = 16; o; o >>= 1)
        ss += __shfl_xor_sync(0xffffffffu, ss, o);
    if ((tid & 31) == 0) partial[tid >> 5] = ss;
    __syncthreads();

    float s = 0.0f;
    #pragma unroll
    for (int w = 0; w < 8; w++) s += partial[w];

    const float inv = 1.0f / fmaxf(sqrtf(s), 1e-12f);
    const float s2 = __ldg(scales + 1);

    float* orow = out + (size_t)row * OUT_ROW;
    const float xn = v * inv;
    if (tid < DD) {
        xsrep[tid]          = xn;
        xsrep[RS + tid]     = xn;
        xsrep[2 * RS + tid] = xn;
        xsrep[3 * RS + tid] = xn;
        xs2[tid] = xn * s2;
        orow[tid] = xn;              // degree-1 features (unscaled)
    }
    __syncthreads();

    // ---- degree-2: flat aligned-quad stream ----
    // t in [0, NTRIU); segment i covers [base(i), base(i)+DD-i), base(i)=i*(257-i)/2.
    // Per quad: i = floor((257 - sqrt(257^2-8t))/2 + 3e-4). Approx-sqrt safety:
    // interior points are >= 0.0078 below the next integer; approx error <= ~6e-5;
    // the +3e-4 bias absorbs the boundary (exact-square) case. Exact for all t.
    float* odeg2 = orow + DD;
    const int lane = tid & 31;
    const float* xj = xsrep + (lane >> 3) * RS;   // this lane's replica

    for (int q = tid; q < NQ; q += 256) {
        const int t = 4 * q;
        const float disc = (float)(66049 - 8 * t);       // 257^2 - 8t, exact in fp32
        const float rt = disc * rsqrt_approx(disc);      // ~sqrt(disc)
        int i = (int)((257.0f - rt) * 0.5f + 3e-4f);
        const int base = (i * (257 - i)) >> 1;
        int j = i + (t - base);
        float a = xs2[i];                                // one load per quad (mostly)

        float4 o;
        o.x = a * xj[j];
        if (++j >= DD) { i++; j = i; a = xs2[i]; }
        o.y = a * xj[j];
        if (++j >= DD) { i++; j = i; a = xs2[i]; }
        o.z = a * xj[j];
        if (++j >= DD) { i++; j = i; a = xs2[i]; }
        o.w = a * xj[j];

        __stcs(reinterpret_cast<float4*>(odeg2 + t), o);
    }
}

extern "C" void kernel_launch(void* const* d_in, const int* in_sizes, int n_in,
                              void* d_out, int out_size) {
    const float* x      = (const float*)d_in[0];
    const float* scales = (const float*)d_in[1];
    float* out          = (float*)d_out;
    poly_kernel<<<ROWS, 256>>>(x, scales, out);
}